// round 10
// baseline (speedup 1.0000x reference)
#include <cuda_runtime.h>
#include <cstdint>
#include <cstddef>

#define LORA_SCALING 4.0f   // alpha/rank = 32/8

// ---------------------------------------------------------------------------
// Static scratch: tf32-pre-rounded, k-permuted, LoRA-embedded operands
//   xe[M][K+32]: cols [0,K) = tf32(x) k-perm; cols [K,K+32) = perm pad of T=(x@A)*s
//   we[N][K+32]: cols [0,K) = tf32(W^T) k-perm; cols [K,K+32) = perm pad of loraB^T
// ---------------------------------------------------------------------------
#define MAX_M 8192
#define MAX_K 1600
#define MAX_N 4800
__device__ float g_xe[(size_t)MAX_M * (MAX_K + 32)];
__device__ float g_we[(size_t)MAX_N * (MAX_K + 32)];

__device__ __forceinline__ uint32_t f2tf32(float f) {
    uint32_t u;
    asm("cvt.rna.tf32.f32 %0, %1;" : "=r"(u) : "f"(f));
    return u;
}
// k-permutation within a 32-tile: orig k = ks*8 + half*4 + t4 -> t4*8 + ks*2 + half
__host__ __device__ __forceinline__ int kperm(int k) {
    return (k & 3) * 8 + ((k >> 3) << 1) + ((k >> 2) & 1);
}

// ---------------------------------------------------------------------------
// Pre-pass 1 (fused): xe row <- tf32 perm of x row; xe[row][K+..] <- perm pad T
// One warp per row.
// ---------------------------------------------------------------------------
template <int R>
__global__ void lora_xa_fused(const float* __restrict__ x,
                              const float* __restrict__ A,
                              float* __restrict__ xe,
                              int M, int K, int KE, float scale) {
    extern __shared__ float As[];  // [R][K]
    int tid = threadIdx.x;
    for (int i = tid; i < K * R; i += blockDim.x) {
        int k = i / R, r = i - k * R;
        As[r * K + k] = A[i];
    }
    __syncthreads();

    int w = tid >> 5, lane = tid & 31;
    int row = blockIdx.x * (blockDim.x >> 5) + w;
    if (row >= M) return;

    const float* xr = x + (size_t)row * K;
    float* xer = xe + (size_t)row * KE;
    const int kp = kperm(lane);

    float acc[R];
#pragma unroll
    for (int r = 0; r < R; r++) acc[r] = 0.f;

    for (int k = lane; k < K; k += 32) {
        float xv = xr[k];
        xer[(k & ~31) + kp] = __uint_as_float(f2tf32(xv));
#pragma unroll
        for (int r = 0; r < R; r++) acc[r] += xv * As[r * K + k];
    }
#pragma unroll
    for (int r = 0; r < R; r++)
#pragma unroll
        for (int off = 16; off; off >>= 1)
            acc[r] += __shfl_down_sync(0xffffffffu, acc[r], off);
    if (lane == 0) {
#pragma unroll
        for (int p = 0; p < 32; p++) xer[K + p] = 0.f;
#pragma unroll
        for (int r = 0; r < R; r++)
            xer[K + kperm(r)] = __uint_as_float(f2tf32(acc[r] * scale));
    }
}

__global__ void lora_xa_fused_gen(const float* __restrict__ x,
                                  const float* __restrict__ A,
                                  float* __restrict__ xe,
                                  int M, int K, int KE, int R, float scale) {
    extern __shared__ float As[];
    int tid = threadIdx.x;
    for (int i = tid; i < K * R; i += blockDim.x) {
        int k = i / R, r = i - k * R;
        As[r * K + k] = A[i];
    }
    __syncthreads();
    int w = tid >> 5, lane = tid & 31;
    int row = blockIdx.x * (blockDim.x >> 5) + w;
    if (row >= M) return;
    const float* xr = x + (size_t)row * K;
    float* xer = xe + (size_t)row * KE;
    const int kp = kperm(lane);
    float acc[32];
    for (int r = 0; r < 32; r++) acc[r] = 0.f;
    for (int k = lane; k < K; k += 32) {
        float xv = xr[k];
        xer[(k & ~31) + kp] = __uint_as_float(f2tf32(xv));
        for (int r = 0; r < R; r++) acc[r] += xv * As[r * K + k];
    }
    for (int r = 0; r < 32; r++) {
        for (int off = 16; off; off >>= 1)
            acc[r] += __shfl_down_sync(0xffffffffu, acc[r], off);
    }
    if (lane == 0) {
        for (int p = 0; p < 32; p++) xer[K + p] = 0.f;
        for (int r = 0; r < R && r < 32; r++)
            xer[K + kperm(r)] = __uint_as_float(f2tf32(acc[r] * scale));
    }
}

// ---------------------------------------------------------------------------
// Pre-pass 2: we[n][tile + kperm] = tf32(W[k][n])  (32x32 smem transpose)
// ---------------------------------------------------------------------------
__global__ void wt_cvt_perm(const float* __restrict__ W, float* __restrict__ we,
                            int K, int N, int KE) {
    __shared__ float tile[32][33];
    int k0 = blockIdx.y * 32, n0 = blockIdx.x * 32;
    int tx = threadIdx.x, ty = threadIdx.y;
#pragma unroll
    for (int i = 0; i < 32; i += 8)
        tile[ty + i][tx] = W[(size_t)(k0 + ty + i) * N + n0 + tx];
    __syncthreads();
    int kp = kperm(tx);
#pragma unroll
    for (int i = 0; i < 32; i += 8)
        we[(size_t)(n0 + ty + i) * KE + k0 + kp] =
            __uint_as_float(f2tf32(tile[tx][ty + i]));
}

// Pre-pass 3: we[n][K + kperm(r)] = tf32(loraB[r][n]); zero elsewhere
__global__ void bembed_kernel(const float* __restrict__ lB, float* __restrict__ we,
                              int N, int K, int KE, int R) {
    int n = blockIdx.x * blockDim.x + threadIdx.x;
    if (n >= N) return;
    float* wr = we + (size_t)n * KE + K;
#pragma unroll
    for (int p = 0; p < 32; p++) wr[p] = 0.f;
    for (int r = 0; r < R && r < 32; r++)
        wr[kperm(r)] = __uint_as_float(f2tf32(lB[(size_t)r * N + n]));
}

// ---------------------------------------------------------------------------
// GEMM: out[M][N] = xe @ we^T + bias.  TF32 mma.sync m16n8k8.
// BM=128 BN=96 BK=32, 384 thr (12 warps 4m x 3n, warp tile 32x32), 3-stage.
// Both A and B fragments via LDS.128 (shared k-perm); exact tiling, no guards.
// ---------------------------------------------------------------------------
#define BM 128
#define BN 96
#define BK 32
#define TSTRIDE 36                     // floats per smem row (32 + 4 pad)
#define ROWB (TSTRIDE * 4)             // 144 bytes
#define A_FLOATS (BM * TSTRIDE)        // 4608
#define B_FLOATS (BN * TSTRIDE)        // 3456
#define A_BYTES (A_FLOATS * 4)         // 18432
#define STAGE_BYTES ((A_FLOATS + B_FLOATS) * 4)   // 32256
#define N_STAGES 3
#define GEMM_SMEM (N_STAGES * STAGE_BYTES)        // 96768

__device__ __forceinline__ void mma_tf32(float* c, const uint32_t* a, const uint32_t* b) {
    asm volatile(
        "mma.sync.aligned.m16n8k8.row.col.f32.tf32.tf32.f32 "
        "{%0,%1,%2,%3}, {%4,%5,%6,%7}, {%8,%9}, {%0,%1,%2,%3};"
        : "+f"(c[0]), "+f"(c[1]), "+f"(c[2]), "+f"(c[3])
        : "r"(a[0]), "r"(a[1]), "r"(a[2]), "r"(a[3]), "r"(b[0]), "r"(b[1]));
}
__device__ __forceinline__ void cp_async16(uint32_t dst, const void* src) {
    asm volatile("cp.async.cg.shared.global [%0], [%1], 16;\n" :: "r"(dst), "l"(src));
}
__device__ __forceinline__ uint4 lds128(uint32_t addr) {
    uint4 v;
    asm volatile("ld.shared.v4.b32 {%0,%1,%2,%3}, [%4];"
                 : "=r"(v.x), "=r"(v.y), "=r"(v.z), "=r"(v.w) : "r"(addr));
    return v;
}

__global__ __launch_bounds__(384, 2)
void lora_gemm_kernel(const float* __restrict__ xe, const float* __restrict__ we,
                      const float* __restrict__ bias, float* __restrict__ out,
                      int M, int N, int KE) {
    extern __shared__ float smem[];
    const uint32_t sb = (uint32_t)__cvta_generic_to_shared(smem);

    const int tid = threadIdx.x;
    const int m0 = blockIdx.y * BM;
    const int n0 = blockIdx.x * BN;
    const int KT = KE / BK;            // 51 uniform tiles (LoRA embedded)

    // --- per-thread cp.async coordinates (A: 1024 chunks, B: 768 chunks) ---
    const float* srcA[3];
    uint32_t dstA[3];
#pragma unroll
    for (int j = 0; j < 3; j++) {
        int c = tid + j * 384;
        int r = c >> 3, q = (c & 7) * 4;
        srcA[j] = xe + (size_t)(m0 + (r & 127)) * KE + q;
        dstA[j] = (r & 127) * ROWB + q * 4;     // byte offset within A region
    }
    const bool a2ok = (tid < 256);              // chunk 1024..1151 invalid
    const float* srcB[2];
    uint32_t dstB[2];
#pragma unroll
    for (int j = 0; j < 2; j++) {
        int c = tid + j * 384;
        int r = c >> 3, q = (c & 7) * 4;
        srcB[j] = we + (size_t)(n0 + r) * KE + q;
        dstB[j] = A_BYTES + r * ROWB + q * 4;
    }

    auto prefetch = [&](int kt, uint32_t stOff) {
        const int k0 = kt * BK;
        uint32_t base = sb + stOff;
        cp_async16(base + dstA[0], srcA[0] + k0);
        cp_async16(base + dstA[1], srcA[1] + k0);
        if (a2ok) cp_async16(base + dstA[2], srcA[2] + k0);
        cp_async16(base + dstB[0], srcB[0] + k0);
        cp_async16(base + dstB[1], srcB[1] + k0);
        asm volatile("cp.async.commit_group;\n" ::: "memory");
    };

    // --- warp layout: 12 warps = 4(m) x 3(n), warp tile 32x32 ---
    const int w = tid >> 5, lane = tid & 31;
    const int wm = (w & 3) * 32;
    const int wn = (w >> 2) * 32;
    const int g = lane >> 2, t4 = lane & 3;

    const uint32_t aOff = ((wm + g) * TSTRIDE + t4 * 8) * 4;            // A frag base
    const uint32_t bOff = (uint32_t)A_BYTES + ((wn + g) * TSTRIDE + t4 * 8) * 4;

    float acc[2][4][4];
#pragma unroll
    for (int mi = 0; mi < 2; mi++)
#pragma unroll
        for (int ni = 0; ni < 4; ni++)
#pragma unroll
            for (int e = 0; e < 4; e++) acc[mi][ni][e] = 0.f;

    prefetch(0, 0);
    prefetch(1, STAGE_BYTES);

    uint32_t so = 0;                       // stage of current tile kt
    uint32_t soP = 2 * STAGE_BYTES;        // stage of tile kt+2 (prefetch target)
    for (int kt = 0; kt < KT; kt++) {
        asm volatile("cp.async.wait_group 1;\n" ::: "memory");
        __syncthreads();
        if (kt + 2 < KT) prefetch(kt + 2, soP);
        else asm volatile("cp.async.commit_group;\n" ::: "memory");  // keep count

        const uint32_t aB = sb + so + aOff;
        const uint32_t bB = sb + so + bOff;
#pragma unroll
        for (int ks2 = 0; ks2 < 2; ks2++) {
            uint4 va[2][2], vb[4];
#pragma unroll
            for (int mi = 0; mi < 2; mi++) {
                va[mi][0] = lds128(aB + mi * (16 * ROWB) + ks2 * 16);
                va[mi][1] = lds128(aB + mi * (16 * ROWB) + 8 * ROWB + ks2 * 16);
            }
#pragma unroll
            for (int ni = 0; ni < 4; ni++)
                vb[ni] = lds128(bB + ni * (8 * ROWB) + ks2 * 16);
#pragma unroll
            for (int sub = 0; sub < 2; sub++) {
#pragma unroll
                for (int mi = 0; mi < 2; mi++) {
                    uint32_t afr[4];
                    if (sub == 0) {
                        afr[0] = va[mi][0].x; afr[1] = va[mi][1].x;
                        afr[2] = va[mi][0].y; afr[3] = va[mi][1].y;
                    } else {
                        afr[0] = va[mi][0].z; afr[1] = va[mi][1].z;
                        afr[2] = va[mi][0].w; afr[3] = va[mi][1].w;
                    }
#pragma unroll
                    for (int ni = 0; ni < 4; ni++) {
                        uint32_t bfr[2];
                        if (sub == 0) { bfr[0] = vb[ni].x; bfr[1] = vb[ni].y; }
                        else          { bfr[0] = vb[ni].z; bfr[1] = vb[ni].w; }
                        mma_tf32(acc[mi][ni], afr, bfr);
                    }
                }
            }
        }
        // FIX (R6 bug): advance BOTH stage pointers by one stage per iteration.
        so += STAGE_BYTES;
        if (so == N_STAGES * STAGE_BYTES) so = 0;
        soP += STAGE_BYTES;
        if (soP == N_STAGES * STAGE_BYTES) soP = 0;
    }

    // --- epilogue: bias + float2 stores (exact tiling, no guards) ---
#pragma unroll
    for (int mi = 0; mi < 2; mi++) {
        int r0 = m0 + wm + mi * 16 + g;
        int r1 = r0 + 8;
#pragma unroll
        for (int ni = 0; ni < 4; ni++) {
            int c = n0 + wn + ni * 8 + 2 * t4;
            float bv0 = __ldg(bias + c);
            float bv1 = __ldg(bias + c + 1);
            float2 v0 = make_float2(acc[mi][ni][0] + bv0, acc[mi][ni][1] + bv1);
            float2 v1 = make_float2(acc[mi][ni][2] + bv0, acc[mi][ni][3] + bv1);
            *reinterpret_cast<float2*>(out + (size_t)r0 * N + c) = v0;
            *reinterpret_cast<float2*>(out + (size_t)r1 * N + c) = v1;
        }
    }
}

// ---------------------------------------------------------------------------
extern "C" void kernel_launch(void* const* d_in, const int* in_sizes, int n_in,
                              void* d_out, int out_size) {
    const float* x  = (const float*)d_in[0];
    const float* W  = (const float*)d_in[1];
    const float* b  = (const float*)d_in[2];
    const float* lA = (const float*)d_in[3];
    const float* lB = (const float*)d_in[4];
    float* out = (float*)d_out;

    const int Dout = in_sizes[2];
    const int Din  = in_sizes[1] / Dout;
    const int R    = in_sizes[3] / Din;
    const int M    = in_sizes[0] / Din;
    const int N    = Dout;
    const int K    = Din;
    const int KE   = K + 32;

    float *xe, *we;
    cudaGetSymbolAddress((void**)&xe, g_xe);
    cudaGetSymbolAddress((void**)&we, g_we);

    // 1) xe = tf32-perm(x) with LoRA T embedded in last 32 cols
    {
        const int threads = 512;               // 16 rows/block
        const int grid = (M + 15) / 16;
        const size_t smem = (size_t)R * K * sizeof(float);
        if (R == 8) {
            cudaFuncSetAttribute(lora_xa_fused<8>, cudaFuncAttributeMaxDynamicSharedMemorySize, (int)smem);
            lora_xa_fused<8><<<grid, threads, smem>>>(x, lA, xe, M, K, KE, LORA_SCALING);
        } else if (R == 16) {
            cudaFuncSetAttribute(lora_xa_fused<16>, cudaFuncAttributeMaxDynamicSharedMemorySize, (int)smem);
            lora_xa_fused<16><<<grid, threads, smem>>>(x, lA, xe, M, K, KE, LORA_SCALING);
        } else if (R == 4) {
            cudaFuncSetAttribute(lora_xa_fused<4>, cudaFuncAttributeMaxDynamicSharedMemorySize, (int)smem);
            lora_xa_fused<4><<<grid, threads, smem>>>(x, lA, xe, M, K, KE, LORA_SCALING);
        } else {
            cudaFuncSetAttribute(lora_xa_fused_gen, cudaFuncAttributeMaxDynamicSharedMemorySize, (int)smem);
            lora_xa_fused_gen<<<grid, threads, smem>>>(x, lA, xe, M, K, KE, R, LORA_SCALING);
        }
    }
    // 2) we = tf32-perm(W^T)
    {
        dim3 blk(32, 8), grd(N / 32, K / 32);
        wt_cvt_perm<<<grd, blk>>>(W, we, K, N, KE);
    }
    // 3) loraB embedded in we's last 32 cols
    bembed_kernel<<<(N + 255) / 256, 256>>>(lB, we, N, K, KE, R);

    // 4) GEMM (exact tiling: M%128==0, N%96==0, KE%32==0 for this problem)
    {
        cudaFuncSetAttribute(lora_gemm_kernel, cudaFuncAttributeMaxDynamicSharedMemorySize, GEMM_SMEM);
        dim3 grid(N / BN, M / BM);
        lora_gemm_kernel<<<grid, 384, GEMM_SMEM>>>(xe, we, b, out, M, N, KE);
    }
}

// round 14
// speedup vs baseline: 1.9130x; 1.9130x over previous
#include <cuda_runtime.h>
#include <cuda_fp16.h>
#include <cstdint>
#include <cstddef>

#define LORA_SCALING 4.0f   // alpha/rank = 32/8

// ---------------------------------------------------------------------------
// Static scratch: fp16 (RNE) operands, k-perm16'd, LoRA embedded
//   xe[M][K+64]: [0,K) = fp16(x); [K,K+64) = perm pad of T=(x@A)*s
//   we[N][K+64]: [0,K) = fp16(W^T); [K,K+64) = perm pad of loraB^T
// In-row layout: 64-elem tiles; within each 32-elem subchunk, kperm16.
// ---------------------------------------------------------------------------
#define MAX_M 8192
#define MAX_K 1600
#define MAX_N 4800
__device__ __align__(256) __half g_xe[(size_t)MAX_M * (MAX_K + 64)];
__device__ __align__(256) __half g_we[(size_t)MAX_N * (MAX_K + 64)];

// k within a 32-chunk -> position so that thread t4's 8 halfs (two k16 steps)
// are contiguous 16B:  k = s*16 + hi*8 + 2*t4 + b  ->  t4*8 + s*4 + hi*2 + b
__host__ __device__ __forceinline__ int kperm16(int k) {
    return ((k >> 1) & 3) * 8 + ((k >> 4) & 1) * 4 + ((k >> 3) & 1) * 2 + (k & 1);
}
// full in-row position for k within a 64-elem row tile
__host__ __device__ __forceinline__ int rowpos(int k) {
    return (k & ~63) + (((k >> 5) & 1) << 5) + kperm16(k & 31);
}

// ---------------------------------------------------------------------------
// Pre-pass 1 (fused): xe row <- fp16 perm of x row; xe[row][K..K+64) <- perm T
// One warp per row.
// ---------------------------------------------------------------------------
template <int R>
__global__ void lora_xa_fused(const float* __restrict__ x,
                              const float* __restrict__ A,
                              __half* __restrict__ xe,
                              int M, int K, int KE, float scale) {
    extern __shared__ float As[];  // [R][K]
    int tid = threadIdx.x;
    for (int i = tid; i < K * R; i += blockDim.x) {
        int k = i / R, r = i - k * R;
        As[r * K + k] = A[i];
    }
    __syncthreads();

    int w = tid >> 5, lane = tid & 31;
    int row = blockIdx.x * (blockDim.x >> 5) + w;
    if (row >= M) return;

    const float* xr = x + (size_t)row * K;
    __half* xer = xe + (size_t)row * KE;
    const int kp = kperm16(lane);   // (k & 31) == lane for lane-strided k

    float acc[R];
#pragma unroll
    for (int r = 0; r < R; r++) acc[r] = 0.f;

    for (int k = lane; k < K; k += 32) {
        float xv = xr[k];
        xer[(k & ~63) + (((k >> 5) & 1) << 5) + kp] = __float2half_rn(xv);
#pragma unroll
        for (int r = 0; r < R; r++) acc[r] += xv * As[r * K + k];
    }
#pragma unroll
    for (int r = 0; r < R; r++)
#pragma unroll
        for (int off = 16; off; off >>= 1)
            acc[r] += __shfl_down_sync(0xffffffffu, acc[r], off);
    if (lane == 0) {
#pragma unroll
        for (int p = 0; p < 64; p++) xer[K + p] = __float2half_rn(0.f);
#pragma unroll
        for (int r = 0; r < R; r++)
            xer[K + rowpos(r)] = __float2half_rn(acc[r] * scale);
    }
}

__global__ void lora_xa_fused_gen(const float* __restrict__ x,
                                  const float* __restrict__ A,
                                  __half* __restrict__ xe,
                                  int M, int K, int KE, int R, float scale) {
    extern __shared__ float As[];
    int tid = threadIdx.x;
    for (int i = tid; i < K * R; i += blockDim.x) {
        int k = i / R, r = i - k * R;
        As[r * K + k] = A[i];
    }
    __syncthreads();
    int w = tid >> 5, lane = tid & 31;
    int row = blockIdx.x * (blockDim.x >> 5) + w;
    if (row >= M) return;
    const float* xr = x + (size_t)row * K;
    __half* xer = xe + (size_t)row * KE;
    const int kp = kperm16(lane);
    float acc[32];
    for (int r = 0; r < 32; r++) acc[r] = 0.f;
    for (int k = lane; k < K; k += 32) {
        float xv = xr[k];
        xer[(k & ~63) + (((k >> 5) & 1) << 5) + kp] = __float2half_rn(xv);
        for (int r = 0; r < R; r++) acc[r] += xv * As[r * K + k];
    }
    for (int r = 0; r < 32; r++) {
        for (int off = 16; off; off >>= 1)
            acc[r] += __shfl_down_sync(0xffffffffu, acc[r], off);
    }
    if (lane == 0) {
        for (int p = 0; p < 64; p++) xer[K + p] = __float2half_rn(0.f);
        for (int r = 0; r < R && r < 32; r++)
            xer[K + rowpos(r)] = __float2half_rn(acc[r] * scale);
    }
}

// ---------------------------------------------------------------------------
// Pre-pass 2: we[n][rowpos(k)] = fp16(W[k][n])   (32x32 smem transpose)
// ---------------------------------------------------------------------------
__global__ void wt_cvt_perm(const float* __restrict__ W, __half* __restrict__ we,
                            int K, int N, int KE) {
    __shared__ float tile[32][33];
    int k0 = blockIdx.y * 32, n0 = blockIdx.x * 32;
    int tx = threadIdx.x, ty = threadIdx.y;
#pragma unroll
    for (int i = 0; i < 32; i += 8)
        tile[ty + i][tx] = W[(size_t)(k0 + ty + i) * N + n0 + tx];
    __syncthreads();
    int pos = (k0 & ~63) + (((k0 >> 5) & 1) << 5) + kperm16(tx);
#pragma unroll
    for (int i = 0; i < 32; i += 8)
        we[(size_t)(n0 + ty + i) * KE + pos] = __float2half_rn(tile[tx][ty + i]);
}

// Pre-pass 3: we[n][K + rowpos(r)] = fp16(loraB[r][n]); zero elsewhere
__global__ void bembed_kernel(const float* __restrict__ lB, __half* __restrict__ we,
                              int N, int K, int KE, int R) {
    int n = blockIdx.x * blockDim.x + threadIdx.x;
    if (n >= N) return;
    __half* wr = we + (size_t)n * KE + K;
#pragma unroll
    for (int p = 0; p < 64; p++) wr[p] = __float2half_rn(0.f);
    for (int r = 0; r < R && r < 32; r++)
        wr[rowpos(r)] = __float2half_rn(lB[(size_t)r * N + n]);
}

// ---------------------------------------------------------------------------
// GEMM: out[M][N] = xe @ we^T + bias.  FP16 mma.sync m16n8k16, fp32 accum.
// BM=128 BN=96 BK=64(elems)=128B rows, 384 thr (12 warps 4m x 3n, 32x32 tile),
// 4-stage cp.async pipeline. XOR-swizzled 128B smem rows, zero padding.
// Swizzle: chunk ch of row r stored at ((ch ^ ((r&1)<<2)) << 4).
// ---------------------------------------------------------------------------
#define BM 128
#define BN 96
#define A_BYTES (BM * 128)             // 16384
#define B_BYTES (BN * 128)             // 12288
#define STAGE_BYTES (A_BYTES + B_BYTES)  // 28672
#define N_STAGES 4
#define GEMM_SMEM (N_STAGES * STAGE_BYTES)  // 114688

__device__ __forceinline__ void mma_f16(float* c, uint32_t a0, uint32_t a1,
                                        uint32_t a2, uint32_t a3,
                                        uint32_t b0, uint32_t b1) {
    asm volatile(
        "mma.sync.aligned.m16n8k16.row.col.f32.f16.f16.f32 "
        "{%0,%1,%2,%3}, {%4,%5,%6,%7}, {%8,%9}, {%0,%1,%2,%3};"
        : "+f"(c[0]), "+f"(c[1]), "+f"(c[2]), "+f"(c[3])
        : "r"(a0), "r"(a1), "r"(a2), "r"(a3), "r"(b0), "r"(b1));
}
__device__ __forceinline__ void cp_async16(uint32_t dst, const void* src) {
    asm volatile("cp.async.cg.shared.global [%0], [%1], 16;\n" :: "r"(dst), "l"(src));
}
__device__ __forceinline__ uint4 lds128(uint32_t addr) {
    uint4 v;
    asm volatile("ld.shared.v4.b32 {%0,%1,%2,%3}, [%4];"
                 : "=r"(v.x), "=r"(v.y), "=r"(v.z), "=r"(v.w) : "r"(addr));
    return v;
}

__global__ __launch_bounds__(384, 2)
void lora_gemm_kernel(const __half* __restrict__ xe, const __half* __restrict__ we,
                      const float* __restrict__ bias, float* __restrict__ out,
                      int M, int N, int KE) {
    extern __shared__ float smem[];
    const uint32_t sb = (uint32_t)__cvta_generic_to_shared(smem);

    const int tid = threadIdx.x;
    const int m0 = blockIdx.y * BM;
    const int n0 = blockIdx.x * BN;
    const int KT = KE / 64;            // 26 uniform tiles (LoRA embedded)

    // --- per-thread cp.async coords.  A: 1024 16B-chunks, B: 768 ---
    const __half* srcA[3];
    uint32_t dstA[3];
#pragma unroll
    for (int j = 0; j < 3; j++) {
        int c = tid + j * 384;
        int r = (c >> 3) & 127, ch = c & 7;
        srcA[j] = xe + (size_t)(m0 + r) * KE + ch * 8;
        dstA[j] = r * 128 + ((ch ^ ((r & 1) << 2)) << 4);
    }
    const bool a2ok = (tid < 256);
    const __half* srcB[2];
    uint32_t dstB[2];
#pragma unroll
    for (int j = 0; j < 2; j++) {
        int c = tid + j * 384;
        int r = c >> 3, ch = c & 7;
        srcB[j] = we + (size_t)(n0 + r) * KE + ch * 8;
        dstB[j] = A_BYTES + r * 128 + ((ch ^ ((r & 1) << 2)) << 4);
    }

    auto prefetch = [&](int kt, uint32_t stOff) {
        const int k0 = kt * 64;
        uint32_t base = sb + stOff;
        cp_async16(base + dstA[0], srcA[0] + k0);
        cp_async16(base + dstA[1], srcA[1] + k0);
        if (a2ok) cp_async16(base + dstA[2], srcA[2] + k0);
        cp_async16(base + dstB[0], srcB[0] + k0);
        cp_async16(base + dstB[1], srcB[1] + k0);
        asm volatile("cp.async.commit_group;\n" ::: "memory");
    };

    // --- warp layout: 12 warps = 4(m) x 3(n), warp tile 32x32 ---
    const int w = tid >> 5, lane = tid & 31;
    const int wm = (w & 3) * 32;
    const int wn = (w >> 2) * 32;
    const int g = lane >> 2, t4 = lane & 3;

    // Fragment bases: base = row*128 + t4*16; subchunk c of a parity-p row
    // lives at (c ^ p) * 64 (matches the cp.async store swizzle).
    const uint32_t p = (uint32_t)(g & 1);
    const uint32_t aOff = (uint32_t)((wm + g) * 128 + t4 * 16);
    const uint32_t bOff = (uint32_t)A_BYTES + (uint32_t)((wn + g) * 128 + t4 * 16);
    const uint32_t cO[2] = {p * 64, (1u - p) * 64};

    float acc[2][4][4];
#pragma unroll
    for (int mi = 0; mi < 2; mi++)
#pragma unroll
        for (int ni = 0; ni < 4; ni++)
#pragma unroll
            for (int e = 0; e < 4; e++) acc[mi][ni][e] = 0.f;

    prefetch(0, 0);
    prefetch(1, STAGE_BYTES);
    prefetch(2, 2 * STAGE_BYTES);

    uint32_t so = 0;                       // stage of current tile kt
    uint32_t soP = 3 * STAGE_BYTES;        // stage of tile kt+3
    for (int kt = 0; kt < KT; kt++) {
        asm volatile("cp.async.wait_group 2;\n" ::: "memory");
        __syncthreads();
        if (kt + 3 < KT) prefetch(kt + 3, soP);
        else asm volatile("cp.async.commit_group;\n" ::: "memory");  // keep count

        const uint32_t aB = sb + so + aOff;
        const uint32_t bB = sb + so + bOff;
#pragma unroll
        for (int c = 0; c < 2; c++) {            // two 32-elem subchunks
            uint4 vg[2], vh[2], vb[4];
#pragma unroll
            for (int mi = 0; mi < 2; mi++) {
                vg[mi] = lds128(aB + mi * 2048 + cO[c]);          // row g
                vh[mi] = lds128(aB + mi * 2048 + 1024 + cO[c]);   // row g+8
            }
#pragma unroll
            for (int ni = 0; ni < 4; ni++)
                vb[ni] = lds128(bB + ni * 1024 + cO[c]);
#pragma unroll
            for (int s = 0; s < 2; s++) {        // two k16 steps per subchunk
#pragma unroll
                for (int mi = 0; mi < 2; mi++) {
                    uint32_t a0 = s ? vg[mi].z : vg[mi].x;
                    uint32_t a1 = s ? vh[mi].z : vh[mi].x;
                    uint32_t a2 = s ? vg[mi].w : vg[mi].y;
                    uint32_t a3 = s ? vh[mi].w : vh[mi].y;
#pragma unroll
                    for (int ni = 0; ni < 4; ni++) {
                        uint32_t b0 = s ? vb[ni].z : vb[ni].x;
                        uint32_t b1 = s ? vb[ni].w : vb[ni].y;
                        mma_f16(acc[mi][ni], a0, a1, a2, a3, b0, b1);
                    }
                }
            }
        }
        so += STAGE_BYTES;
        if (so == N_STAGES * STAGE_BYTES) so = 0;
        soP += STAGE_BYTES;
        if (soP == N_STAGES * STAGE_BYTES) soP = 0;
    }

    // --- epilogue: bias + float2 stores (exact tiling, no guards) ---
#pragma unroll
    for (int mi = 0; mi < 2; mi++) {
        int r0 = m0 + wm + mi * 16 + g;
        int r1 = r0 + 8;
#pragma unroll
        for (int ni = 0; ni < 4; ni++) {
            int cc = n0 + wn + ni * 8 + 2 * t4;
            float bv0 = __ldg(bias + cc);
            float bv1 = __ldg(bias + cc + 1);
            float2 v0 = make_float2(acc[mi][ni][0] + bv0, acc[mi][ni][1] + bv1);
            float2 v1 = make_float2(acc[mi][ni][2] + bv0, acc[mi][ni][3] + bv1);
            *reinterpret_cast<float2*>(out + (size_t)r0 * N + cc) = v0;
            *reinterpret_cast<float2*>(out + (size_t)r1 * N + cc) = v1;
        }
    }
}

// ---------------------------------------------------------------------------
extern "C" void kernel_launch(void* const* d_in, const int* in_sizes, int n_in,
                              void* d_out, int out_size) {
    const float* x  = (const float*)d_in[0];
    const float* W  = (const float*)d_in[1];
    const float* b  = (const float*)d_in[2];
    const float* lA = (const float*)d_in[3];
    const float* lB = (const float*)d_in[4];
    float* out = (float*)d_out;

    const int Dout = in_sizes[2];
    const int Din  = in_sizes[1] / Dout;
    const int R    = in_sizes[3] / Din;
    const int M    = in_sizes[0] / Din;
    const int N    = Dout;
    const int K    = Din;
    const int KE   = K + 64;

    __half *xe, *we;
    cudaGetSymbolAddress((void**)&xe, g_xe);
    cudaGetSymbolAddress((void**)&we, g_we);

    // 1) xe = fp16-perm(x) with LoRA T embedded in last 64 cols
    {
        const int threads = 512;               // 16 rows/block
        const int grid = (M + 15) / 16;
        const size_t smem = (size_t)R * K * sizeof(float);
        if (R == 8) {
            cudaFuncSetAttribute(lora_xa_fused<8>, cudaFuncAttributeMaxDynamicSharedMemorySize, (int)smem);
            lora_xa_fused<8><<<grid, threads, smem>>>(x, lA, xe, M, K, KE, LORA_SCALING);
        } else if (R == 16) {
            cudaFuncSetAttribute(lora_xa_fused<16>, cudaFuncAttributeMaxDynamicSharedMemorySize, (int)smem);
            lora_xa_fused<16><<<grid, threads, smem>>>(x, lA, xe, M, K, KE, LORA_SCALING);
        } else if (R == 4) {
            cudaFuncSetAttribute(lora_xa_fused<4>, cudaFuncAttributeMaxDynamicSharedMemorySize, (int)smem);
            lora_xa_fused<4><<<grid, threads, smem>>>(x, lA, xe, M, K, KE, LORA_SCALING);
        } else {
            cudaFuncSetAttribute(lora_xa_fused_gen, cudaFuncAttributeMaxDynamicSharedMemorySize, (int)smem);
            lora_xa_fused_gen<<<grid, threads, smem>>>(x, lA, xe, M, K, KE, R, LORA_SCALING);
        }
    }
    // 2) we = fp16-perm(W^T)
    {
        dim3 blk(32, 8), grd(N / 32, K / 32);
        wt_cvt_perm<<<grd, blk>>>(W, we, K, N, KE);
    }
    // 3) loraB embedded in we's last 64 cols
    bembed_kernel<<<(N + 255) / 256, 256>>>(lB, we, N, K, KE, R);

    // 4) GEMM (exact tiling: M%128==0, N%96==0, KE%64==0 for this problem)
    {
        cudaFuncSetAttribute(lora_gemm_kernel, cudaFuncAttributeMaxDynamicSharedMemorySize, GEMM_SMEM);
        dim3 grid(N / BN, M / BM);
        lora_gemm_kernel<<<grid, 384, GEMM_SMEM>>>(xe, we, b, out, M, N, KE);
    }
}

// round 15
// speedup vs baseline: 2.1432x; 1.1204x over previous
#include <cuda_runtime.h>
#include <cuda_fp16.h>
#include <cstdint>
#include <cstddef>

#define LORA_SCALING 4.0f   // alpha/rank = 32/8

// ---------------------------------------------------------------------------
// Static scratch: fp16 (RNE) operands, k-perm16'd, LoRA embedded
//   xe[M][K+64]: [0,K) = fp16(x); [K,K+64) = perm pad of T=(x@A)*s
//   we[N][K+64]: [0,K) = fp16(W^T); [K,K+64) = perm pad of loraB^T
// ---------------------------------------------------------------------------
#define MAX_M 8192
#define MAX_K 1600
#define MAX_N 4800
__device__ __align__(256) __half g_xe[(size_t)MAX_M * (MAX_K + 64)];
__device__ __align__(256) __half g_we[(size_t)MAX_N * (MAX_K + 64)];

// k within a 32-chunk -> position so that thread t4's 8 halfs (two k16 steps)
// are contiguous 16B:  k = s*16 + hi*8 + 2*t4 + b  ->  t4*8 + s*4 + hi*2 + b
__host__ __device__ __forceinline__ int kperm16(int k) {
    return ((k >> 1) & 3) * 8 + ((k >> 4) & 1) * 4 + ((k >> 3) & 1) * 2 + (k & 1);
}
// full in-row position for k within a 64-elem row tile
__host__ __device__ __forceinline__ int rowpos(int k) {
    return (k & ~63) + (((k >> 5) & 1) << 5) + kperm16(k & 31);
}

// ---------------------------------------------------------------------------
// Pre-pass 1 (fused): xe row <- fp16 perm of x row; xe[row][K..K+64) <- perm T
// One warp per row.
// ---------------------------------------------------------------------------
template <int R>
__global__ void lora_xa_fused(const float* __restrict__ x,
                              const float* __restrict__ A,
                              __half* __restrict__ xe,
                              int M, int K, int KE, float scale) {
    extern __shared__ float As[];  // [R][K]
    int tid = threadIdx.x;
    for (int i = tid; i < K * R; i += blockDim.x) {
        int k = i / R, r = i - k * R;
        As[r * K + k] = A[i];
    }
    __syncthreads();

    int w = tid >> 5, lane = tid & 31;
    int row = blockIdx.x * (blockDim.x >> 5) + w;
    if (row >= M) return;

    const float* xr = x + (size_t)row * K;
    __half* xer = xe + (size_t)row * KE;
    const int kp = kperm16(lane);   // (k & 31) == lane for lane-strided k

    float acc[R];
#pragma unroll
    for (int r = 0; r < R; r++) acc[r] = 0.f;

    for (int k = lane; k < K; k += 32) {
        float xv = xr[k];
        xer[(k & ~63) + (((k >> 5) & 1) << 5) + kp] = __float2half_rn(xv);
#pragma unroll
        for (int r = 0; r < R; r++) acc[r] += xv * As[r * K + k];
    }
#pragma unroll
    for (int r = 0; r < R; r++)
#pragma unroll
        for (int off = 16; off; off >>= 1)
            acc[r] += __shfl_down_sync(0xffffffffu, acc[r], off);
    if (lane == 0) {
#pragma unroll
        for (int p = 0; p < 64; p++) xer[K + p] = __float2half_rn(0.f);
#pragma unroll
        for (int r = 0; r < R; r++)
            xer[K + rowpos(r)] = __float2half_rn(acc[r] * scale);
    }
}

__global__ void lora_xa_fused_gen(const float* __restrict__ x,
                                  const float* __restrict__ A,
                                  __half* __restrict__ xe,
                                  int M, int K, int KE, int R, float scale) {
    extern __shared__ float As[];
    int tid = threadIdx.x;
    for (int i = tid; i < K * R; i += blockDim.x) {
        int k = i / R, r = i - k * R;
        As[r * K + k] = A[i];
    }
    __syncthreads();
    int w = tid >> 5, lane = tid & 31;
    int row = blockIdx.x * (blockDim.x >> 5) + w;
    if (row >= M) return;
    const float* xr = x + (size_t)row * K;
    __half* xer = xe + (size_t)row * KE;
    const int kp = kperm16(lane);
    float acc[32];
    for (int r = 0; r < 32; r++) acc[r] = 0.f;
    for (int k = lane; k < K; k += 32) {
        float xv = xr[k];
        xer[(k & ~63) + (((k >> 5) & 1) << 5) + kp] = __float2half_rn(xv);
        for (int r = 0; r < R; r++) acc[r] += xv * As[r * K + k];
    }
    for (int r = 0; r < 32; r++) {
        for (int off = 16; off; off >>= 1)
            acc[r] += __shfl_down_sync(0xffffffffu, acc[r], off);
    }
    if (lane == 0) {
        for (int p = 0; p < 64; p++) xer[K + p] = __float2half_rn(0.f);
        for (int r = 0; r < R && r < 32; r++)
            xer[K + rowpos(r)] = __float2half_rn(acc[r] * scale);
    }
}

// ---------------------------------------------------------------------------
// Pre-pass 2: we[n][rowpos(k)] = fp16(W[k][n])   (32x32 smem transpose)
// ---------------------------------------------------------------------------
__global__ void wt_cvt_perm(const float* __restrict__ W, __half* __restrict__ we,
                            int K, int N, int KE) {
    __shared__ float tile[32][33];
    int k0 = blockIdx.y * 32, n0 = blockIdx.x * 32;
    int tx = threadIdx.x, ty = threadIdx.y;
#pragma unroll
    for (int i = 0; i < 32; i += 8)
        tile[ty + i][tx] = W[(size_t)(k0 + ty + i) * N + n0 + tx];
    __syncthreads();
    int pos = (k0 & ~63) + (((k0 >> 5) & 1) << 5) + kperm16(tx);
#pragma unroll
    for (int i = 0; i < 32; i += 8)
        we[(size_t)(n0 + ty + i) * KE + pos] = __float2half_rn(tile[tx][ty + i]);
}

// Pre-pass 3: we[n][K + rowpos(r)] = fp16(loraB[r][n]); zero elsewhere
__global__ void bembed_kernel(const float* __restrict__ lB, __half* __restrict__ we,
                              int N, int K, int KE, int R) {
    int n = blockIdx.x * blockDim.x + threadIdx.x;
    if (n >= N) return;
    __half* wr = we + (size_t)n * KE + K;
#pragma unroll
    for (int p = 0; p < 64; p++) wr[p] = __float2half_rn(0.f);
    for (int r = 0; r < R && r < 32; r++)
        wr[rowpos(r)] = __float2half_rn(lB[(size_t)r * N + n]);
}

// ---------------------------------------------------------------------------
// GEMM: out[M][N] = xe @ we^T + bias.  FP16 mma.sync m16n8k16, fp32 accum.
// BM=128 BN=96 BK=64(elems)=128B rows.
// 256 thr / 8 warps (2m x 4n), warp tile 64x24 -> 128 regs/thread at 2 CTA/SM.
// 4-stage cp.async pipeline. XOR-swizzled 128B smem rows.
// Swizzle: chunk ch of row r stored at ((ch ^ ((r&1)<<2)) << 4).
// ---------------------------------------------------------------------------
#define BM 128
#define BN 96
#define A_BYTES (BM * 128)             // 16384
#define B_BYTES (BN * 128)             // 12288
#define STAGE_BYTES (A_BYTES + B_BYTES)  // 28672
#define N_STAGES 4
#define GEMM_SMEM (N_STAGES * STAGE_BYTES)  // 114688

__device__ __forceinline__ void mma_f16(float* c, uint32_t a0, uint32_t a1,
                                        uint32_t a2, uint32_t a3,
                                        uint32_t b0, uint32_t b1) {
    asm volatile(
        "mma.sync.aligned.m16n8k16.row.col.f32.f16.f16.f32 "
        "{%0,%1,%2,%3}, {%4,%5,%6,%7}, {%8,%9}, {%0,%1,%2,%3};"
        : "+f"(c[0]), "+f"(c[1]), "+f"(c[2]), "+f"(c[3])
        : "r"(a0), "r"(a1), "r"(a2), "r"(a3), "r"(b0), "r"(b1));
}
__device__ __forceinline__ void cp_async16(uint32_t dst, const void* src) {
    asm volatile("cp.async.cg.shared.global [%0], [%1], 16;\n" :: "r"(dst), "l"(src));
}
__device__ __forceinline__ uint4 lds128(uint32_t addr) {
    uint4 v;
    asm volatile("ld.shared.v4.b32 {%0,%1,%2,%3}, [%4];"
                 : "=r"(v.x), "=r"(v.y), "=r"(v.z), "=r"(v.w) : "r"(addr));
    return v;
}

__global__ __launch_bounds__(256, 2)
void lora_gemm_kernel(const __half* __restrict__ xe, const __half* __restrict__ we,
                      const float* __restrict__ bias, float* __restrict__ out,
                      int M, int N, int KE) {
    extern __shared__ float smem[];
    const uint32_t sb = (uint32_t)__cvta_generic_to_shared(smem);

    const int tid = threadIdx.x;
    const int m0 = blockIdx.y * BM;
    const int n0 = blockIdx.x * BN;
    const int KT = KE / 64;            // 26 uniform tiles (LoRA embedded)

    // --- per-thread cp.async coords.  A: 1024 16B-chunks (4/thr), B: 768 (3/thr)
    const __half* srcA[4];
    uint32_t dstA[4];
#pragma unroll
    for (int j = 0; j < 4; j++) {
        int c = tid + j * 256;
        int r = c >> 3, ch = c & 7;
        srcA[j] = xe + (size_t)(m0 + r) * KE + ch * 8;
        dstA[j] = r * 128 + ((ch ^ ((r & 1) << 2)) << 4);
    }
    const __half* srcB[3];
    uint32_t dstB[3];
#pragma unroll
    for (int j = 0; j < 3; j++) {
        int c = tid + j * 256;
        int r = c >> 3, ch = c & 7;
        srcB[j] = we + (size_t)(n0 + r) * KE + ch * 8;
        dstB[j] = A_BYTES + r * 128 + ((ch ^ ((r & 1) << 2)) << 4);
    }

    auto prefetch = [&](int kt, uint32_t stOff) {
        const int k0 = kt * 64;
        uint32_t base = sb + stOff;
#pragma unroll
        for (int j = 0; j < 4; j++) cp_async16(base + dstA[j], srcA[j] + k0);
#pragma unroll
        for (int j = 0; j < 3; j++) cp_async16(base + dstB[j], srcB[j] + k0);
        asm volatile("cp.async.commit_group;\n" ::: "memory");
    };

    // --- warp layout: 8 warps = 2(m) x 4(n), warp tile 64x24 ---
    const int w = tid >> 5, lane = tid & 31;
    const int wm = (w & 1) * 64;           // 2 m-warps
    const int wn = (w >> 1) * 24;          // 4 n-warps
    const int g = lane >> 2, t4 = lane & 3;

    // Fragment bases: base = row*128 + t4*16; subchunk c of a parity-p row
    // lives at (c ^ p) * 64 (matches the cp.async store swizzle).
    const uint32_t p = (uint32_t)(g & 1);
    const uint32_t aOff = (uint32_t)((wm + g) * 128 + t4 * 16);
    const uint32_t bOff = (uint32_t)A_BYTES + (uint32_t)((wn + g) * 128 + t4 * 16);
    const uint32_t cO[2] = {p * 64, (1u - p) * 64};

    float acc[4][3][4];
#pragma unroll
    for (int mi = 0; mi < 4; mi++)
#pragma unroll
        for (int ni = 0; ni < 3; ni++)
#pragma unroll
            for (int e = 0; e < 4; e++) acc[mi][ni][e] = 0.f;

    prefetch(0, 0);
    prefetch(1, STAGE_BYTES);
    prefetch(2, 2 * STAGE_BYTES);

    uint32_t so = 0;                       // stage of current tile kt
    uint32_t soP = 3 * STAGE_BYTES;        // stage of tile kt+3
    for (int kt = 0; kt < KT; kt++) {
        asm volatile("cp.async.wait_group 2;\n" ::: "memory");
        __syncthreads();
        if (kt + 3 < KT) prefetch(kt + 3, soP);
        else asm volatile("cp.async.commit_group;\n" ::: "memory");  // keep count

        const uint32_t aB = sb + so + aOff;
        const uint32_t bB = sb + so + bOff;
#pragma unroll
        for (int c = 0; c < 2; c++) {            // two 32-elem subchunks
            uint4 vg[4], vh[4], vb[3];
#pragma unroll
            for (int mi = 0; mi < 4; mi++) {
                vg[mi] = lds128(aB + mi * 2048 + cO[c]);          // row g
                vh[mi] = lds128(aB + mi * 2048 + 1024 + cO[c]);   // row g+8
            }
#pragma unroll
            for (int ni = 0; ni < 3; ni++)
                vb[ni] = lds128(bB + ni * 1024 + cO[c]);
#pragma unroll
            for (int s = 0; s < 2; s++) {        // two k16 steps per subchunk
#pragma unroll
                for (int mi = 0; mi < 4; mi++) {
                    uint32_t a0 = s ? vg[mi].z : vg[mi].x;
                    uint32_t a1 = s ? vh[mi].z : vh[mi].x;
                    uint32_t a2 = s ? vg[mi].w : vg[mi].y;
                    uint32_t a3 = s ? vh[mi].w : vh[mi].y;
#pragma unroll
                    for (int ni = 0; ni < 3; ni++) {
                        uint32_t b0 = s ? vb[ni].z : vb[ni].x;
                        uint32_t b1 = s ? vb[ni].w : vb[ni].y;
                        mma_f16(acc[mi][ni], a0, a1, a2, a3, b0, b1);
                    }
                }
            }
        }
        so += STAGE_BYTES;
        if (so == N_STAGES * STAGE_BYTES) so = 0;
        soP += STAGE_BYTES;
        if (soP == N_STAGES * STAGE_BYTES) soP = 0;
    }

    // --- epilogue: bias + float2 stores (exact tiling, no guards) ---
#pragma unroll
    for (int mi = 0; mi < 4; mi++) {
        int r0 = m0 + wm + mi * 16 + g;
        int r1 = r0 + 8;
#pragma unroll
        for (int ni = 0; ni < 3; ni++) {
            int cc = n0 + wn + ni * 8 + 2 * t4;
            float bv0 = __ldg(bias + cc);
            float bv1 = __ldg(bias + cc + 1);
            float2 v0 = make_float2(acc[mi][ni][0] + bv0, acc[mi][ni][1] + bv1);
            float2 v1 = make_float2(acc[mi][ni][2] + bv0, acc[mi][ni][3] + bv1);
            *reinterpret_cast<float2*>(out + (size_t)r0 * N + cc) = v0;
            *reinterpret_cast<float2*>(out + (size_t)r1 * N + cc) = v1;
        }
    }
}

// ---------------------------------------------------------------------------
extern "C" void kernel_launch(void* const* d_in, const int* in_sizes, int n_in,
                              void* d_out, int out_size) {
    const float* x  = (const float*)d_in[0];
    const float* W  = (const float*)d_in[1];
    const float* b  = (const float*)d_in[2];
    const float* lA = (const float*)d_in[3];
    const float* lB = (const float*)d_in[4];
    float* out = (float*)d_out;

    const int Dout = in_sizes[2];
    const int Din  = in_sizes[1] / Dout;
    const int R    = in_sizes[3] / Din;
    const int M    = in_sizes[0] / Din;
    const int N    = Dout;
    const int K    = Din;
    const int KE   = K + 64;

    __half *xe, *we;
    cudaGetSymbolAddress((void**)&xe, g_xe);
    cudaGetSymbolAddress((void**)&we, g_we);

    // 1) xe = fp16-perm(x) with LoRA T embedded in last 64 cols
    {
        const int threads = 512;               // 16 rows/block
        const int grid = (M + 15) / 16;
        const size_t smem = (size_t)R * K * sizeof(float);
        if (R == 8) {
            cudaFuncSetAttribute(lora_xa_fused<8>, cudaFuncAttributeMaxDynamicSharedMemorySize, (int)smem);
            lora_xa_fused<8><<<grid, threads, smem>>>(x, lA, xe, M, K, KE, LORA_SCALING);
        } else if (R == 16) {
            cudaFuncSetAttribute(lora_xa_fused<16>, cudaFuncAttributeMaxDynamicSharedMemorySize, (int)smem);
            lora_xa_fused<16><<<grid, threads, smem>>>(x, lA, xe, M, K, KE, LORA_SCALING);
        } else if (R == 4) {
            cudaFuncSetAttribute(lora_xa_fused<4>, cudaFuncAttributeMaxDynamicSharedMemorySize, (int)smem);
            lora_xa_fused<4><<<grid, threads, smem>>>(x, lA, xe, M, K, KE, LORA_SCALING);
        } else {
            cudaFuncSetAttribute(lora_xa_fused_gen, cudaFuncAttributeMaxDynamicSharedMemorySize, (int)smem);
            lora_xa_fused_gen<<<grid, threads, smem>>>(x, lA, xe, M, K, KE, R, LORA_SCALING);
        }
    }
    // 2) we = fp16-perm(W^T)
    {
        dim3 blk(32, 8), grd(N / 32, K / 32);
        wt_cvt_perm<<<grd, blk>>>(W, we, K, N, KE);
    }
    // 3) loraB embedded in we's last 64 cols
    bembed_kernel<<<(N + 255) / 256, 256>>>(lB, we, N, K, KE, R);

    // 4) GEMM (exact tiling: M%128==0, N%96==0, KE%64==0 for this problem)
    {
        cudaFuncSetAttribute(lora_gemm_kernel, cudaFuncAttributeMaxDynamicSharedMemorySize, GEMM_SMEM);
        dim3 grid(N / BN, M / BM);
        lora_gemm_kernel<<<grid, 256, GEMM_SMEM>>>(xe, we, b, out, M, N, KE);
    }
}